// round 4
// baseline (speedup 1.0000x reference)
#include <cuda_runtime.h>
#include <cstdint>
#include <cstddef>

#define NNODES 10000
#define NEDGES 640000
#define HID    128
#define OUTD   10

// Scratch: PQ[n][0:128] = x[n] @ W1[0:128,:]            (P)
//          PQ[n][128:256] = x[n] @ W1[128:256,:] + b1   (Q', b1 folded in)
__device__ float g_PQ[NNODES * 256];

// ---------- packed f32x2 helpers ----------
__device__ __forceinline__ unsigned long long f2_pack1(float v) {
    unsigned long long d;
    unsigned int u = __float_as_uint(v);
    asm("mov.b64 %0, {%1, %2};" : "=l"(d) : "r"(u), "r"(u));
    return d;
}
__device__ __forceinline__ unsigned long long f2_make(float a, float b) {
    unsigned long long d;
    unsigned int ua = __float_as_uint(a), ub = __float_as_uint(b);
    asm("mov.b64 %0, {%1, %2};" : "=l"(d) : "r"(ua), "r"(ub));
    return d;
}
__device__ __forceinline__ unsigned long long f2_fma(unsigned long long a,
                                                     unsigned long long b,
                                                     unsigned long long c) {
    unsigned long long d;
    asm("fma.rn.f32x2 %0, %1, %2, %3;" : "=l"(d) : "l"(a), "l"(b), "l"(c));
    return d;
}
__device__ __forceinline__ unsigned long long f2_add(unsigned long long a,
                                                     unsigned long long b) {
    unsigned long long d;
    asm("add.rn.f32x2 %0, %1, %2;" : "=l"(d) : "l"(a), "l"(b));
    return d;
}
__device__ __forceinline__ void f2_unpack(unsigned long long v, float& lo, float& hi) {
    unsigned int a, b;
    asm("mov.b64 {%0, %1}, %2;" : "=r"(a), "=r"(b) : "l"(v));
    lo = __uint_as_float(a);
    hi = __uint_as_float(b);
}

// ============================================================================
// Phase 1: PQ = x @ [W1a | W1b], b1 folded into the Q (second) half.
// M=10000, N=256, K=128. BM=BN=BK=64; 256 threads; 4x4 per thread.
// ============================================================================
__global__ void __launch_bounds__(256) phase1_kernel(const float* __restrict__ x,
                                                     const float* __restrict__ W1,
                                                     const float* __restrict__ b1) {
    __shared__ float As[64][68];
    __shared__ float Bs[64][68];

    const int tid = threadIdx.x;
    const int m0 = blockIdx.x * 64;
    const int n0 = blockIdx.y * 64;
    const int tr = (tid >> 4) << 2;
    const int tc = (tid & 15) << 2;

    const int wRow = (n0 < 128) ? 0 : 128;
    const int wCol = (n0 < 128) ? n0 : (n0 - 128);

    float acc[4][4] = {};

    for (int k0 = 0; k0 < 128; k0 += 64) {
        #pragma unroll
        for (int i = 0; i < 4; i++) {
            int idx = tid + i * 256;
            int m = idx >> 4, kq = idx & 15;
            int gm = m0 + m;
            float4 v = make_float4(0.f, 0.f, 0.f, 0.f);
            if (gm < NNODES) v = *(const float4*)(x + (size_t)gm * HID + k0 + kq * 4);
            *(float4*)&As[m][kq * 4] = v;
        }
        #pragma unroll
        for (int i = 0; i < 4; i++) {
            int idx = tid + i * 256;
            int kk = idx >> 4, cq = idx & 15;
            float4 v = *(const float4*)(W1 + (size_t)(k0 + kk + wRow) * HID + wCol + cq * 4);
            *(float4*)&Bs[kk][cq * 4] = v;
        }
        __syncthreads();

        #pragma unroll
        for (int k = 0; k < 64; k++) {
            float4 b = *(const float4*)&Bs[k][tc];
            float a0 = As[tr + 0][k];
            float a1 = As[tr + 1][k];
            float a2 = As[tr + 2][k];
            float a3 = As[tr + 3][k];
            acc[0][0] += a0 * b.x; acc[0][1] += a0 * b.y; acc[0][2] += a0 * b.z; acc[0][3] += a0 * b.w;
            acc[1][0] += a1 * b.x; acc[1][1] += a1 * b.y; acc[1][2] += a1 * b.z; acc[1][3] += a1 * b.w;
            acc[2][0] += a2 * b.x; acc[2][1] += a2 * b.y; acc[2][2] += a2 * b.z; acc[2][3] += a2 * b.w;
            acc[3][0] += a3 * b.x; acc[3][1] += a3 * b.y; acc[3][2] += a3 * b.z; acc[3][3] += a3 * b.w;
        }
        __syncthreads();
    }

    // Fold b1 into Q half
    float4 bv = make_float4(0.f, 0.f, 0.f, 0.f);
    if (n0 >= 128) bv = *(const float4*)(b1 + wCol + tc);

    #pragma unroll
    for (int r = 0; r < 4; r++) {
        int gm = m0 + tr + r;
        if (gm < NNODES) {
            *(float4*)(g_PQ + (size_t)gm * 256 + n0 + tc) =
                make_float4(acc[r][0] + bv.x, acc[r][1] + bv.y,
                            acc[r][2] + bv.z, acc[r][3] + bv.w);
        }
    }
}

// ============================================================================
// Phase 2: direct-gather compute. Warp = 4 edges x 8 lanes.
// Lane (g,s): g = lane>>3 (edge), s = lane&7 (j-octant).
// Gather: LDG.128 index (8k+s) -> one full 128B line per edge per instr.
// W2: 4 replicas in smem, packed 12-float rows (no overlap). Replica c = s>>1,
// replica stride 1540 floats = 6160 B == 16 B (mod 128). Lane byte addr
// mod 128 = 16*(s>>1) + 64*(s&1): the 8 s-lanes cover the 8 distinct 16B
// windows of a 128B phase; same-s lanes broadcast. Conflict-free LDS.128.
// ============================================================================
#define P2_THREADS 512
#define P2_EPB 64            // 16 warps * 4 edges
#define W2_REP_STRIDE 1540   // floats per replica (6160 B)

__global__ void __launch_bounds__(P2_THREADS) phase2_kernel(const int* __restrict__ ei,
                                                            const float* __restrict__ W2,
                                                            const float* __restrict__ b2,
                                                            float* __restrict__ out) {
    __shared__ float w2s[4 * W2_REP_STRIDE + 8];   // ~24.7 KB

    const int tid = threadIdx.x;

    // Stage 4 replicas: idx = c*128 + j  (512 rows total, one per thread)
    {
        int c = tid >> 7, j = tid & 127;
        float* dstr = w2s + c * W2_REP_STRIDE + 12 * j;
        const float* srcr = W2 + j * OUTD;
        #pragma unroll
        for (int o = 0; o < OUTD; o++) dstr[o] = srcr[o];
    }
    __syncthreads();

    const int warp = tid >> 5, lane = tid & 31;
    const int g = lane >> 3, s = lane & 7;
    const int e = blockIdx.x * P2_EPB + warp * 4 + g;

    const int src = ei[e];
    const int dst = ei[NEDGES + e];
    const float4* Prow = (const float4*)(g_PQ + (size_t)src * 256);
    const float4* Qrow = (const float4*)(g_PQ + (size_t)dst * 256) + 32;

    // Prefetch full gather (MLP=8)
    float4 p[4], q[4];
    #pragma unroll
    for (int k = 0; k < 4; k++) { p[k] = Prow[8 * k + s]; }
    #pragma unroll
    for (int k = 0; k < 4; k++) { q[k] = Qrow[8 * k + s]; }

    const float* w2base = w2s + (s >> 1) * W2_REP_STRIDE;

    unsigned long long acc0 = 0ull, acc1 = 0ull, acc2 = 0ull, acc3 = 0ull, acc4 = 0ull;

    #pragma unroll
    for (int k = 0; k < 4; k++) {
        float hv[4];
        hv[0] = fmaxf(p[k].x + q[k].x, 0.f);
        hv[1] = fmaxf(p[k].y + q[k].y, 0.f);
        hv[2] = fmaxf(p[k].z + q[k].z, 0.f);
        hv[3] = fmaxf(p[k].w + q[k].w, 0.f);
        const int jbase = 32 * k + 4 * s;
        #pragma unroll
        for (int i = 0; i < 4; i++) {
            const float* w = w2base + 12 * (jbase + i);
            float4 wa = *(const float4*)w;          // LDS.128
            float4 wb = *(const float4*)(w + 4);    // LDS.128
            float2 wc = *(const float2*)(w + 8);    // LDS.64
            unsigned long long vv = f2_pack1(hv[i]);
            acc0 = f2_fma(vv, f2_make(wa.x, wa.y), acc0);
            acc1 = f2_fma(vv, f2_make(wa.z, wa.w), acc1);
            acc2 = f2_fma(vv, f2_make(wb.x, wb.y), acc2);
            acc3 = f2_fma(vv, f2_make(wb.z, wb.w), acc3);
            acc4 = f2_fma(vv, f2_make(wc.x, wc.y), acc4);
        }
    }

    // Reduce over the 8 s-lanes of each octet (xor 1,2,4 stays in octet)
    #pragma unroll
    for (int m = 1; m <= 4; m <<= 1) {
        acc0 = f2_add(acc0, __shfl_xor_sync(0xFFFFFFFFu, acc0, m));
        acc1 = f2_add(acc1, __shfl_xor_sync(0xFFFFFFFFu, acc1, m));
        acc2 = f2_add(acc2, __shfl_xor_sync(0xFFFFFFFFu, acc2, m));
        acc3 = f2_add(acc3, __shfl_xor_sync(0xFFFFFFFFu, acc3, m));
        acc4 = f2_add(acc4, __shfl_xor_sync(0xFFFFFFFFu, acc4, m));
    }

    if (s < 5) {
        unsigned long long r;
        switch (s) {
            case 0: r = acc0; break;
            case 1: r = acc1; break;
            case 2: r = acc2; break;
            case 3: r = acc3; break;
            default: r = acc4; break;
        }
        float lo, hi;
        f2_unpack(r, lo, hi);
        float2 res = make_float2(lo + b2[2 * s], hi + b2[2 * s + 1]);
        *(float2*)(out + (size_t)e * OUTD + s * 2) = res;
    }
}

// ============================================================================
extern "C" void kernel_launch(void* const* d_in, const int* in_sizes, int n_in,
                              void* d_out, int out_size) {
    const float* x  = (const float*)d_in[0];
    const int*   ei = (const int*)d_in[1];
    const float* W1 = (const float*)d_in[2];
    const float* b1 = (const float*)d_in[3];
    const float* W2 = (const float*)d_in[4];
    const float* b2 = (const float*)d_in[5];
    float* out = (float*)d_out;

    dim3 g1((NNODES + 63) / 64, 256 / 64);
    phase1_kernel<<<g1, 256>>>(x, W1, b1);

    phase2_kernel<<<NEDGES / P2_EPB, P2_THREADS>>>(ei, W2, b2, out);
}

// round 5
// speedup vs baseline: 1.5012x; 1.5012x over previous
#include <cuda_runtime.h>
#include <cstdint>
#include <cstddef>

#define NNODES 10000
#define NEDGES 640000
#define HID    128
#define OUTD   10

// Scratch: PQ[n][0:128] = x[n] @ W1[0:128,:]            (P)
//          PQ[n][128:256] = x[n] @ W1[128:256,:] + b1   (Q', b1 folded in)
__device__ float g_PQ[NNODES * 256];

// ---------- packed f32x2 helpers ----------
__device__ __forceinline__ unsigned long long f2_pack1(float v) {
    unsigned long long d;
    unsigned int u = __float_as_uint(v);
    asm("mov.b64 %0, {%1, %2};" : "=l"(d) : "r"(u), "r"(u));
    return d;
}
__device__ __forceinline__ unsigned long long f2_make(float a, float b) {
    unsigned long long d;
    unsigned int ua = __float_as_uint(a), ub = __float_as_uint(b);
    asm("mov.b64 %0, {%1, %2};" : "=l"(d) : "r"(ua), "r"(ub));
    return d;
}
__device__ __forceinline__ unsigned long long f2_fma(unsigned long long a,
                                                     unsigned long long b,
                                                     unsigned long long c) {
    unsigned long long d;
    asm("fma.rn.f32x2 %0, %1, %2, %3;" : "=l"(d) : "l"(a), "l"(b), "l"(c));
    return d;
}
__device__ __forceinline__ unsigned long long f2_add(unsigned long long a,
                                                     unsigned long long b) {
    unsigned long long d;
    asm("add.rn.f32x2 %0, %1, %2;" : "=l"(d) : "l"(a), "l"(b));
    return d;
}
__device__ __forceinline__ void f2_unpack(unsigned long long v, float& lo, float& hi) {
    unsigned int a, b;
    asm("mov.b64 {%0, %1}, %2;" : "=r"(a), "=r"(b) : "l"(v));
    lo = __uint_as_float(a);
    hi = __uint_as_float(b);
}

// ============================================================================
// Phase 1: PQ = x @ [W1a | W1b], b1 folded into the Q (second) half.
// ============================================================================
__global__ void __launch_bounds__(256) phase1_kernel(const float* __restrict__ x,
                                                     const float* __restrict__ W1,
                                                     const float* __restrict__ b1) {
    __shared__ float As[64][68];
    __shared__ float Bs[64][68];

    const int tid = threadIdx.x;
    const int m0 = blockIdx.x * 64;
    const int n0 = blockIdx.y * 64;
    const int tr = (tid >> 4) << 2;
    const int tc = (tid & 15) << 2;

    const int wRow = (n0 < 128) ? 0 : 128;
    const int wCol = (n0 < 128) ? n0 : (n0 - 128);

    float acc[4][4] = {};

    for (int k0 = 0; k0 < 128; k0 += 64) {
        #pragma unroll
        for (int i = 0; i < 4; i++) {
            int idx = tid + i * 256;
            int m = idx >> 4, kq = idx & 15;
            int gm = m0 + m;
            float4 v = make_float4(0.f, 0.f, 0.f, 0.f);
            if (gm < NNODES) v = *(const float4*)(x + (size_t)gm * HID + k0 + kq * 4);
            *(float4*)&As[m][kq * 4] = v;
        }
        #pragma unroll
        for (int i = 0; i < 4; i++) {
            int idx = tid + i * 256;
            int kk = idx >> 4, cq = idx & 15;
            float4 v = *(const float4*)(W1 + (size_t)(k0 + kk + wRow) * HID + wCol + cq * 4);
            *(float4*)&Bs[kk][cq * 4] = v;
        }
        __syncthreads();

        #pragma unroll
        for (int k = 0; k < 64; k++) {
            float4 b = *(const float4*)&Bs[k][tc];
            float a0 = As[tr + 0][k];
            float a1 = As[tr + 1][k];
            float a2 = As[tr + 2][k];
            float a3 = As[tr + 3][k];
            acc[0][0] += a0 * b.x; acc[0][1] += a0 * b.y; acc[0][2] += a0 * b.z; acc[0][3] += a0 * b.w;
            acc[1][0] += a1 * b.x; acc[1][1] += a1 * b.y; acc[1][2] += a1 * b.z; acc[1][3] += a1 * b.w;
            acc[2][0] += a2 * b.x; acc[2][1] += a2 * b.y; acc[2][2] += a2 * b.z; acc[2][3] += a2 * b.w;
            acc[3][0] += a3 * b.x; acc[3][1] += a3 * b.y; acc[3][2] += a3 * b.z; acc[3][3] += a3 * b.w;
        }
        __syncthreads();
    }

    float4 bv = make_float4(0.f, 0.f, 0.f, 0.f);
    if (n0 >= 128) bv = *(const float4*)(b1 + wCol + tc);

    #pragma unroll
    for (int r = 0; r < 4; r++) {
        int gm = m0 + tr + r;
        if (gm < NNODES) {
            *(float4*)(g_PQ + (size_t)gm * 256 + n0 + tc) =
                make_float4(acc[r][0] + bv.x, acc[r][1] + bv.y,
                            acc[r][2] + bv.z, acc[r][3] + bv.w);
        }
    }
}

// ============================================================================
// Phase 2 v3: octet gather, 2 edges per lane, W2 LDS amortized over both.
// Lane (g,s): g = lane>>3, s = lane&7. Edges eA = e0+g, eB = e0+g+4.
// Gather: LDG.128 float4 idx (8k+s): 8 s-lanes = one 128B line per edge.
// W2: 4 replicas, packed 12-float rows, replica c = s>>1, stride 1540 floats
// (6160 B == 16 mod 128): lane addr mod 128 = 16*(s>>1)+64*(s&1), all 8
// distinct 16B windows -> conflict-free; same-s lanes broadcast.
// Each (wa,wb,wc) LDS triple feeds FMAs for BOTH edges (halves LDS/edge).
// 3-level bfly reduce over the octet; lanes s<5 store float2 per edge.
// ============================================================================
#define P2_THREADS 256
#define P2_ITERS 8
#define W2_REP_STRIDE 1540   // floats per replica (6160 B)
// edges per block = 8 warps * 8 edges * 8 iters = 512; blocks = 1250

__global__ void __launch_bounds__(P2_THREADS) phase2_kernel(const int* __restrict__ ei,
                                                            const float* __restrict__ W2,
                                                            const float* __restrict__ b2,
                                                            float* __restrict__ out) {
    __shared__ float w2s[4 * W2_REP_STRIDE + 8];   // ~24.7 KB

    const int tid = threadIdx.x;

    // Stage 4 replicas (512 rows, 2 per thread)
    #pragma unroll
    for (int t = 0; t < 2; t++) {
        int r = tid + t * 256;
        int c = r >> 7, j = r & 127;
        float* dstr = w2s + c * W2_REP_STRIDE + 12 * j;
        const float* srcr = W2 + j * OUTD;
        #pragma unroll
        for (int o = 0; o < OUTD; o++) dstr[o] = srcr[o];
    }
    __syncthreads();

    const int warp = tid >> 5, lane = tid & 31;
    const int g = lane >> 3, s = lane & 7;
    const float* w2base = w2s + (s >> 1) * W2_REP_STRIDE;

    float2 b2v = make_float2(0.f, 0.f);
    if (s < 5) b2v = *(const float2*)(b2 + 2 * s);

    for (int it = 0; it < P2_ITERS; it++) {
        const int e0 = blockIdx.x * 512 + it * 64 + warp * 8 + g;   // eA=e0, eB=e0+4

        const int srcA = ei[e0];
        const int srcB = ei[e0 + 4];
        const int dstA = ei[NEDGES + e0];
        const int dstB = ei[NEDGES + e0 + 4];

        const float4* PA = (const float4*)(g_PQ + (size_t)srcA * 256);
        const float4* QA = (const float4*)(g_PQ + (size_t)dstA * 256) + 32;
        const float4* PB = (const float4*)(g_PQ + (size_t)srcB * 256);
        const float4* QB = (const float4*)(g_PQ + (size_t)dstB * 256) + 32;

        unsigned long long aA0 = 0, aA1 = 0, aA2 = 0, aA3 = 0, aA4 = 0;
        unsigned long long aB0 = 0, aB1 = 0, aB2 = 0, aB3 = 0, aB4 = 0;

        #pragma unroll
        for (int k = 0; k < 4; k++) {
            float4 pA = PA[8 * k + s];
            float4 qA = QA[8 * k + s];
            float4 pB = PB[8 * k + s];
            float4 qB = QB[8 * k + s];

            float hA[4], hB[4];
            hA[0] = fmaxf(pA.x + qA.x, 0.f); hA[1] = fmaxf(pA.y + qA.y, 0.f);
            hA[2] = fmaxf(pA.z + qA.z, 0.f); hA[3] = fmaxf(pA.w + qA.w, 0.f);
            hB[0] = fmaxf(pB.x + qB.x, 0.f); hB[1] = fmaxf(pB.y + qB.y, 0.f);
            hB[2] = fmaxf(pB.z + qB.z, 0.f); hB[3] = fmaxf(pB.w + qB.w, 0.f);

            const int jbase = 32 * k + 4 * s;
            #pragma unroll
            for (int i = 0; i < 4; i++) {
                const float* w = w2base + 12 * (jbase + i);
                float4 wa = *(const float4*)w;          // LDS.128
                float4 wb = *(const float4*)(w + 4);    // LDS.128
                float2 wc = *(const float2*)(w + 8);    // LDS.64
                unsigned long long w01 = f2_make(wa.x, wa.y);
                unsigned long long w23 = f2_make(wa.z, wa.w);
                unsigned long long w45 = f2_make(wb.x, wb.y);
                unsigned long long w67 = f2_make(wb.z, wb.w);
                unsigned long long w89 = f2_make(wc.x, wc.y);
                unsigned long long vA = f2_pack1(hA[i]);
                unsigned long long vB = f2_pack1(hB[i]);
                aA0 = f2_fma(vA, w01, aA0); aB0 = f2_fma(vB, w01, aB0);
                aA1 = f2_fma(vA, w23, aA1); aB1 = f2_fma(vB, w23, aB1);
                aA2 = f2_fma(vA, w45, aA2); aB2 = f2_fma(vB, w45, aB2);
                aA3 = f2_fma(vA, w67, aA3); aB3 = f2_fma(vB, w67, aB3);
                aA4 = f2_fma(vA, w89, aA4); aB4 = f2_fma(vB, w89, aB4);
            }
        }

        // Reduce over the 8 s-lanes of each octet (xor 1,2,4 stays in octet)
        #pragma unroll
        for (int m = 1; m <= 4; m <<= 1) {
            aA0 = f2_add(aA0, __shfl_xor_sync(0xFFFFFFFFu, aA0, m));
            aA1 = f2_add(aA1, __shfl_xor_sync(0xFFFFFFFFu, aA1, m));
            aA2 = f2_add(aA2, __shfl_xor_sync(0xFFFFFFFFu, aA2, m));
            aA3 = f2_add(aA3, __shfl_xor_sync(0xFFFFFFFFu, aA3, m));
            aA4 = f2_add(aA4, __shfl_xor_sync(0xFFFFFFFFu, aA4, m));
            aB0 = f2_add(aB0, __shfl_xor_sync(0xFFFFFFFFu, aB0, m));
            aB1 = f2_add(aB1, __shfl_xor_sync(0xFFFFFFFFu, aB1, m));
            aB2 = f2_add(aB2, __shfl_xor_sync(0xFFFFFFFFu, aB2, m));
            aB3 = f2_add(aB3, __shfl_xor_sync(0xFFFFFFFFu, aB3, m));
            aB4 = f2_add(aB4, __shfl_xor_sync(0xFFFFFFFFu, aB4, m));
        }

        if (s < 5) {
            unsigned long long rA, rB;
            switch (s) {
                case 0: rA = aA0; rB = aB0; break;
                case 1: rA = aA1; rB = aB1; break;
                case 2: rA = aA2; rB = aB2; break;
                case 3: rA = aA3; rB = aB3; break;
                default: rA = aA4; rB = aB4; break;
            }
            float lo, hi;
            f2_unpack(rA, lo, hi);
            *(float2*)(out + (size_t)e0 * OUTD + 2 * s) =
                make_float2(lo + b2v.x, hi + b2v.y);
            f2_unpack(rB, lo, hi);
            *(float2*)(out + (size_t)(e0 + 4) * OUTD + 2 * s) =
                make_float2(lo + b2v.x, hi + b2v.y);
        }
    }
}

// ============================================================================
extern "C" void kernel_launch(void* const* d_in, const int* in_sizes, int n_in,
                              void* d_out, int out_size) {
    const float* x  = (const float*)d_in[0];
    const int*   ei = (const int*)d_in[1];
    const float* W1 = (const float*)d_in[2];
    const float* b1 = (const float*)d_in[3];
    const float* W2 = (const float*)d_in[4];
    const float* b2 = (const float*)d_in[5];
    float* out = (float*)d_out;

    dim3 g1((NNODES + 63) / 64, 256 / 64);
    phase1_kernel<<<g1, 256>>>(x, W1, b1);

    phase2_kernel<<<1250, P2_THREADS>>>(ei, W2, b2, out);
}

// round 6
// speedup vs baseline: 1.5484x; 1.0315x over previous
#include <cuda_runtime.h>
#include <cstdint>
#include <cstddef>

#define NNODES 10000
#define NEDGES 640000
#define HID    128
#define OUTD   10

// Scratch: PQ[n][0:128] = x[n] @ W1[0:128,:]            (P)
//          PQ[n][128:256] = x[n] @ W1[128:256,:] + b1   (Q', b1 folded in)
__device__ float g_PQ[NNODES * 256];

// ---------- packed f32x2 helpers ----------
__device__ __forceinline__ unsigned long long f2_pack1(float v) {
    unsigned long long d;
    unsigned int u = __float_as_uint(v);
    asm("mov.b64 %0, {%1, %2};" : "=l"(d) : "r"(u), "r"(u));
    return d;
}
__device__ __forceinline__ unsigned long long f2_make(float a, float b) {
    unsigned long long d;
    unsigned int ua = __float_as_uint(a), ub = __float_as_uint(b);
    asm("mov.b64 %0, {%1, %2};" : "=l"(d) : "r"(ua), "r"(ub));
    return d;
}
__device__ __forceinline__ unsigned long long f2_fma(unsigned long long a,
                                                     unsigned long long b,
                                                     unsigned long long c) {
    unsigned long long d;
    asm("fma.rn.f32x2 %0, %1, %2, %3;" : "=l"(d) : "l"(a), "l"(b), "l"(c));
    return d;
}
__device__ __forceinline__ unsigned long long f2_add(unsigned long long a,
                                                     unsigned long long b) {
    unsigned long long d;
    asm("add.rn.f32x2 %0, %1, %2;" : "=l"(d) : "l"(a), "l"(b));
    return d;
}
__device__ __forceinline__ void f2_unpack(unsigned long long v, float& lo, float& hi) {
    unsigned int a, b;
    asm("mov.b64 {%0, %1}, %2;" : "=r"(a), "=r"(b) : "l"(v));
    lo = __uint_as_float(a);
    hi = __uint_as_float(b);
}

// ============================================================================
// Phase 1: PQ = x @ [W1a | W1b], b1 folded into the Q (second) half.
// ============================================================================
__global__ void __launch_bounds__(256) phase1_kernel(const float* __restrict__ x,
                                                     const float* __restrict__ W1,
                                                     const float* __restrict__ b1) {
    __shared__ float As[64][68];
    __shared__ float Bs[64][68];

    const int tid = threadIdx.x;
    const int m0 = blockIdx.x * 64;
    const int n0 = blockIdx.y * 64;
    const int tr = (tid >> 4) << 2;
    const int tc = (tid & 15) << 2;

    const int wRow = (n0 < 128) ? 0 : 128;
    const int wCol = (n0 < 128) ? n0 : (n0 - 128);

    float acc[4][4] = {};

    for (int k0 = 0; k0 < 128; k0 += 64) {
        #pragma unroll
        for (int i = 0; i < 4; i++) {
            int idx = tid + i * 256;
            int m = idx >> 4, kq = idx & 15;
            int gm = m0 + m;
            float4 v = make_float4(0.f, 0.f, 0.f, 0.f);
            if (gm < NNODES) v = *(const float4*)(x + (size_t)gm * HID + k0 + kq * 4);
            *(float4*)&As[m][kq * 4] = v;
        }
        #pragma unroll
        for (int i = 0; i < 4; i++) {
            int idx = tid + i * 256;
            int kk = idx >> 4, cq = idx & 15;
            float4 v = *(const float4*)(W1 + (size_t)(k0 + kk + wRow) * HID + wCol + cq * 4);
            *(float4*)&Bs[kk][cq * 4] = v;
        }
        __syncthreads();

        #pragma unroll
        for (int k = 0; k < 64; k++) {
            float4 b = *(const float4*)&Bs[k][tc];
            float a0 = As[tr + 0][k];
            float a1 = As[tr + 1][k];
            float a2 = As[tr + 2][k];
            float a3 = As[tr + 3][k];
            acc[0][0] += a0 * b.x; acc[0][1] += a0 * b.y; acc[0][2] += a0 * b.z; acc[0][3] += a0 * b.w;
            acc[1][0] += a1 * b.x; acc[1][1] += a1 * b.y; acc[1][2] += a1 * b.z; acc[1][3] += a1 * b.w;
            acc[2][0] += a2 * b.x; acc[2][1] += a2 * b.y; acc[2][2] += a2 * b.z; acc[2][3] += a2 * b.w;
            acc[3][0] += a3 * b.x; acc[3][1] += a3 * b.y; acc[3][2] += a3 * b.z; acc[3][3] += a3 * b.w;
        }
        __syncthreads();
    }

    float4 bv = make_float4(0.f, 0.f, 0.f, 0.f);
    if (n0 >= 128) bv = *(const float4*)(b1 + wCol + tc);

    #pragma unroll
    for (int r = 0; r < 4; r++) {
        int gm = m0 + tr + r;
        if (gm < NNODES) {
            *(float4*)(g_PQ + (size_t)gm * 256 + n0 + tc) =
                make_float4(acc[r][0] + bv.x, acc[r][1] + bv.y,
                            acc[r][2] + bv.z, acc[r][3] + bv.w);
        }
    }
}

// ============================================================================
// Phase 2 v4: W2 resident in REGISTERS (zero inner-loop shared memory).
// Warp = 2 edges: half h = lane>>4 (edge e+h), t = lane&15.
// Lane t owns hidden units j in {4t..4t+3} U {64+4t..64+4t+3}; its W2 slice
// (8 rows x 5 f32x2) lives in 80 registers, loaded once, reused for 64 edges.
// Gather: lane loads P float4 {t, t+16}, Q float4 {32+t, 48+t} of its edge:
// 4 LDG.128 warp-instrs / 2 edges (8 wavefronts/edge = floor).
// Reduce within each 16-lane half: bfly xor8,xor4 on 5 packed accs; lane
// selects r = acc[t>>2]; bfly xor2,xor1 on r and acc4 -> every lane has full
// sums. Lanes (t&3)==0 store out-pairs 0..3; lane t==1 stores pair 4.
// Next edge's p/q prefetched before the FMA/reduce tail (hides L2 latency).
// ============================================================================
#define P2_THREADS 256
#define P2_ITERS 32
// edges/block = 8 warps * 32 iters * 2 = 512; grid = 1250

__global__ void __launch_bounds__(P2_THREADS, 2)
phase2_kernel(const int* __restrict__ ei,
              const float* __restrict__ W2,
              const float* __restrict__ b2,
              float* __restrict__ out) {
    const int tid  = threadIdx.x;
    const int lane = tid & 31;
    const int h    = lane >> 4;
    const int t    = lane & 15;
    const int c    = t >> 2;

    // Load this lane's W2 slice into registers (once; amortized over 64 edges)
    unsigned long long w[8][5];
    #pragma unroll
    for (int i = 0; i < 8; i++) {
        const int j = (i < 4) ? (4 * t + i) : (64 + 4 * t + (i - 4));
        const float* wr = W2 + j * OUTD;
        #pragma unroll
        for (int o2 = 0; o2 < 5; o2++)
            w[i][o2] = f2_make(wr[2 * o2], wr[2 * o2 + 1]);
    }
    const float2 b2r = make_float2(b2[2 * c], b2[2 * c + 1]);
    const float2 b2t = make_float2(b2[8], b2[9]);

    const int e0 = blockIdx.x * 512 + (tid >> 5) * (P2_ITERS * 2);
    const float4* __restrict__ PQ4 = (const float4*)g_PQ;

    // Prologue gather (edge e0+h)
    int src = ei[e0 + h];
    int dst = ei[NEDGES + e0 + h];
    float4 p0 = PQ4[(size_t)src * 64 + t];
    float4 p1 = PQ4[(size_t)src * 64 + 16 + t];
    float4 q0 = PQ4[(size_t)dst * 64 + 32 + t];
    float4 q1 = PQ4[(size_t)dst * 64 + 48 + t];

    for (int it = 0; it < P2_ITERS; it++) {
        const int e = e0 + it * 2 + h;

        // Hidden activations for this lane's 8 j's
        float hv[8];
        hv[0] = fmaxf(p0.x + q0.x, 0.f);
        hv[1] = fmaxf(p0.y + q0.y, 0.f);
        hv[2] = fmaxf(p0.z + q0.z, 0.f);
        hv[3] = fmaxf(p0.w + q0.w, 0.f);
        hv[4] = fmaxf(p1.x + q1.x, 0.f);
        hv[5] = fmaxf(p1.y + q1.y, 0.f);
        hv[6] = fmaxf(p1.z + q1.z, 0.f);
        hv[7] = fmaxf(p1.w + q1.w, 0.f);

        // Prefetch next edge's rows (p/q regs are dead now)
        if (it + 1 < P2_ITERS) {
            src = ei[e0 + (it + 1) * 2 + h];
            dst = ei[NEDGES + e0 + (it + 1) * 2 + h];
            p0 = PQ4[(size_t)src * 64 + t];
            p1 = PQ4[(size_t)src * 64 + 16 + t];
            q0 = PQ4[(size_t)dst * 64 + 32 + t];
            q1 = PQ4[(size_t)dst * 64 + 48 + t];
        }

        // Accumulate 10 outputs as 5 packed f32x2 (all operands in registers)
        unsigned long long a0 = 0, a1 = 0, a2 = 0, a3 = 0, a4 = 0;
        #pragma unroll
        for (int i = 0; i < 8; i++) {
            unsigned long long vv = f2_pack1(hv[i]);
            a0 = f2_fma(vv, w[i][0], a0);
            a1 = f2_fma(vv, w[i][1], a1);
            a2 = f2_fma(vv, w[i][2], a2);
            a3 = f2_fma(vv, w[i][3], a3);
            a4 = f2_fma(vv, w[i][4], a4);
        }

        // Reduce over the 16 lanes of this half
        #pragma unroll
        for (int m = 8; m >= 4; m >>= 1) {
            a0 = f2_add(a0, __shfl_xor_sync(0xFFFFFFFFu, a0, m));
            a1 = f2_add(a1, __shfl_xor_sync(0xFFFFFFFFu, a1, m));
            a2 = f2_add(a2, __shfl_xor_sync(0xFFFFFFFFu, a2, m));
            a3 = f2_add(a3, __shfl_xor_sync(0xFFFFFFFFu, a3, m));
            a4 = f2_add(a4, __shfl_xor_sync(0xFFFFFFFFu, a4, m));
        }
        // Lane's quad handles out-pair c = t>>2 (0..3); a4 handled by all
        unsigned long long r = (c & 2) ? ((c & 1) ? a3 : a2)
                                       : ((c & 1) ? a1 : a0);
        #pragma unroll
        for (int m = 2; m >= 1; m >>= 1) {
            r  = f2_add(r,  __shfl_xor_sync(0xFFFFFFFFu, r,  m));
            a4 = f2_add(a4, __shfl_xor_sync(0xFFFFFFFFu, a4, m));
        }

        float lo, hi;
        if ((t & 3) == 0) {
            f2_unpack(r, lo, hi);
            *(float2*)(out + (size_t)e * OUTD + 2 * c) =
                make_float2(lo + b2r.x, hi + b2r.y);
        }
        if (t == 1) {
            f2_unpack(a4, lo, hi);
            *(float2*)(out + (size_t)e * OUTD + 8) =
                make_float2(lo + b2t.x, hi + b2t.y);
        }
    }
}

// ============================================================================
extern "C" void kernel_launch(void* const* d_in, const int* in_sizes, int n_in,
                              void* d_out, int out_size) {
    const float* x  = (const float*)d_in[0];
    const int*   ei = (const int*)d_in[1];
    const float* W1 = (const float*)d_in[2];
    const float* b1 = (const float*)d_in[3];
    const float* W2 = (const float*)d_in[4];
    const float* b2 = (const float*)d_in[5];
    float* out = (float*)d_out;

    dim3 g1((NNODES + 63) / 64, 256 / 64);
    phase1_kernel<<<g1, 256>>>(x, W1, b1);

    phase2_kernel<<<1250, P2_THREADS>>>(ei, W2, b2, out);
}